// round 3
// baseline (speedup 1.0000x reference)
#include <cuda_runtime.h>

// JPEG compress/decompress (DiffJPEG, factor=1.0) for [16,3,512,512] fp32 in [-1,1].
// One CTA = one 64x64 pixel tile. 3 phases:
//   1) RGB -> YCbCr into smem (swizzled, conflict-free)
//   2) per-thread 8x8 block: DCT -> diff-round quantize -> IDCT, all in registers
//   3) YCbCr -> RGB, clip, store

namespace {

constexpr int Hh = 512;
constexpr int Ww = 512;

// DCT-II basis: Dm[u][x] = cos((2x+1) u pi / 16)
__device__ static constexpr float Dm[8][8] = {
  { 1.f,          1.f,          1.f,          1.f,          1.f,          1.f,          1.f,          1.f         },
  { 0.98078528f,  0.83146961f,  0.55557023f,  0.19509032f, -0.19509032f, -0.55557023f, -0.83146961f, -0.98078528f },
  { 0.92387953f,  0.38268343f, -0.38268343f, -0.92387953f, -0.92387953f, -0.38268343f,  0.38268343f,  0.92387953f },
  { 0.83146961f, -0.19509032f, -0.98078528f, -0.55557023f,  0.55557023f,  0.98078528f,  0.19509032f, -0.83146961f },
  { 0.70710678f, -0.70710678f, -0.70710678f,  0.70710678f,  0.70710678f, -0.70710678f, -0.70710678f,  0.70710678f },
  { 0.55557023f, -0.98078528f,  0.19509032f,  0.83146961f, -0.83146961f, -0.19509032f,  0.98078528f, -0.55557023f },
  { 0.38268343f, -0.92387953f,  0.92387953f, -0.38268343f, -0.38268343f,  0.92387953f, -0.92387953f,  0.38268343f },
  { 0.19509032f, -0.55557023f,  0.83146961f, -0.98078528f,  0.98078528f, -0.83146961f,  0.55557023f, -0.19509032f },
};

__device__ static constexpr float AL[8] = {
  0.70710678118654752f, 1.f, 1.f, 1.f, 1.f, 1.f, 1.f, 1.f
};

__device__ static constexpr float QY[64] = {
  16, 11, 10, 16, 24, 40, 51, 61,
  12, 12, 14, 19, 26, 58, 60, 55,
  14, 13, 16, 24, 40, 57, 69, 56,
  14, 17, 22, 29, 51, 87, 80, 62,
  18, 22, 37, 56, 68, 109, 103, 77,
  24, 35, 55, 64, 81, 104, 113, 92,
  49, 64, 78, 87, 103, 121, 120, 101,
  72, 92, 95, 98, 112, 100, 103, 99
};
__device__ static constexpr float QC[64] = {
  17, 18, 24, 47, 99, 99, 99, 99,
  18, 21, 26, 66, 99, 99, 99, 99,
  24, 26, 56, 99, 99, 99, 99, 99,
  47, 66, 99, 99, 99, 99, 99, 99,
  99, 99, 99, 99, 99, 99, 99, 99,
  99, 99, 99, 99, 99, 99, 99, 99,
  99, 99, 99, 99, 99, 99, 99, 99,
  99, 99, 99, 99, 99, 99, 99, 99
};

// smem column swizzle: XOR bit2 with bit5 so both linear-float4 and
// 8-strided-block float4 accesses are bank-conflict-free.
__device__ __forceinline__ int swz(int row, int c) {
  return row * 64 + (c ^ ((c & 32) >> 3));
}

// 1D 8-point DCT: out[k] = sum_j in[j] * Dm[k][j]  (even/odd split)
__device__ __forceinline__ void dct1(float* v) {
  float e0 = v[0] + v[7], e1 = v[1] + v[6], e2 = v[2] + v[5], e3 = v[3] + v[4];
  float o0 = v[0] - v[7], o1 = v[1] - v[6], o2 = v[2] - v[5], o3 = v[3] - v[4];
  v[0] = (e0 + e3) + (e1 + e2);
  v[4] = Dm[4][0] * ((e0 + e3) - (e1 + e2));
  v[2] = Dm[2][0]*e0 + Dm[2][1]*e1 + Dm[2][2]*e2 + Dm[2][3]*e3;
  v[6] = Dm[6][0]*e0 + Dm[6][1]*e1 + Dm[6][2]*e2 + Dm[6][3]*e3;
  v[1] = Dm[1][0]*o0 + Dm[1][1]*o1 + Dm[1][2]*o2 + Dm[1][3]*o3;
  v[3] = Dm[3][0]*o0 + Dm[3][1]*o1 + Dm[3][2]*o2 + Dm[3][3]*o3;
  v[5] = Dm[5][0]*o0 + Dm[5][1]*o1 + Dm[5][2]*o2 + Dm[5][3]*o3;
  v[7] = Dm[7][0]*o0 + Dm[7][1]*o1 + Dm[7][2]*o2 + Dm[7][3]*o3;
}

// 1D 8-point IDCT: out[k] = sum_j in[j] * Dm[j][k]
__device__ __forceinline__ void idct1(float* v) {
  float i0 = v[0], i1 = v[1], i2 = v[2], i3 = v[3];
  float i4 = v[4], i5 = v[5], i6 = v[6], i7 = v[7];
#pragma unroll
  for (int k = 0; k < 4; ++k) {
    float ev = i0 + Dm[2][k]*i2 + Dm[4][k]*i4 + Dm[6][k]*i6;
    float od = Dm[1][k]*i1 + Dm[3][k]*i3 + Dm[5][k]*i5 + Dm[7][k]*i7;
    v[k]     = ev + od;
    v[7 - k] = ev - od;
  }
}

template <int TAB>
__device__ __forceinline__ void quantize_block(float p[8][8]) {
#pragma unroll
  for (int u = 0; u < 8; ++u) {
#pragma unroll
    for (int v = 0; v < 8; ++v) {
      const float Q = (TAB == 0) ? QY[u * 8 + v] : QC[u * 8 + v];
      const float a = 0.25f * AL[u] * AL[v];
      float s = p[u][v] * (a / Q);        // scaled forward coeff / Q
      float r = rintf(s);                 // round half-to-even == jnp.round
      float d = s - r;
      float q = r + d * d * d;            // diff_round
      p[u][v] = q * (a * Q);              // dequant, fold IDCT alpha*0.25
    }
  }
}

__global__ void __launch_bounds__(256, 2)
jpeg_kernel(const float* __restrict__ in, float* __restrict__ out) {
  __shared__ float sm[3 * 64 * 64];   // exactly 48 KB

  const int tid = threadIdx.x;
  const int gx0 = blockIdx.x * 64;
  const int gy0 = blockIdx.y * 64;
  const size_t plane = (size_t)Hh * Ww;
  const size_t img = (size_t)blockIdx.z * 3 * plane;
  const float* __restrict__ pr = in + img;
  const float* __restrict__ pg = in + img + plane;
  const float* __restrict__ pb = in + img + 2 * plane;

  // ---------------- Phase 1: RGB -> YCbCr into smem ----------------
#pragma unroll
  for (int it = 0; it < 4; ++it) {
    int i = tid + it * 256;             // 0..1023 float4 slots in the tile
    int row = i >> 4;
    int c = (i & 15) << 2;
    size_t g = (size_t)(gy0 + row) * Ww + (gx0 + c);
    float4 r4 = *(const float4*)(pr + g);
    float4 g4 = *(const float4*)(pg + g);
    float4 b4 = *(const float4*)(pb + g);

    float R[4] = { r4.x, r4.y, r4.z, r4.w };
    float G[4] = { g4.x, g4.y, g4.z, g4.w };
    float Bv[4] = { b4.x, b4.y, b4.z, b4.w };
    float Yv[4], Cb[4], Cr[4];
#pragma unroll
    for (int q = 0; q < 4; ++q) {
      float r = fmaf(R[q], 127.5f, 127.5f);   // (x+1)/2*255
      float gg = fmaf(G[q], 127.5f, 127.5f);
      float bb = fmaf(Bv[q], 127.5f, 127.5f);
      Yv[q] = 0.299f * r + 0.587f * gg + 0.114f * bb;
      Cb[q] = -0.168736f * r - 0.331264f * gg + 0.5f * bb + 128.f;
      Cr[q] = 0.5f * r - 0.418688f * gg - 0.081312f * bb + 128.f;
    }
    int sw = swz(row, c);
    *(float4*)&sm[sw]        = make_float4(Yv[0], Yv[1], Yv[2], Yv[3]);
    *(float4*)&sm[4096 + sw] = make_float4(Cb[0], Cb[1], Cb[2], Cb[3]);
    *(float4*)&sm[8192 + sw] = make_float4(Cr[0], Cr[1], Cr[2], Cr[3]);
  }

  __syncthreads();

  // ---------------- Phase 2: per-thread 8x8 DCT/quant/IDCT ----------------
  if (tid < 192) {
    const int k = tid >> 6;             // channel (warp-uniform)
    const int bi = tid & 63;
    const int br = bi >> 3;
    const int bc = bi & 7;
    float* pl = &sm[k * 4096];

    float p[8][8];
#pragma unroll
    for (int r = 0; r < 8; ++r) {
      int R = br * 8 + r;
#pragma unroll
      for (int j = 0; j < 2; ++j) {
        int c = bc * 8 + j * 4;
        float4 v = *(const float4*)&pl[swz(R, c)];
        p[r][j * 4 + 0] = v.x - 128.f;
        p[r][j * 4 + 1] = v.y - 128.f;
        p[r][j * 4 + 2] = v.z - 128.f;
        p[r][j * 4 + 3] = v.w - 128.f;
      }
    }

    // forward DCT (rows then columns)
#pragma unroll
    for (int r = 0; r < 8; ++r) dct1(p[r]);
#pragma unroll
    for (int c = 0; c < 8; ++c) {
      float t[8];
#pragma unroll
      for (int r = 0; r < 8; ++r) t[r] = p[r][c];
      dct1(t);
#pragma unroll
      for (int r = 0; r < 8; ++r) p[r][c] = t[r];
    }

    if (k == 0) quantize_block<0>(p);
    else        quantize_block<1>(p);

    // inverse DCT (rows then columns)
#pragma unroll
    for (int r = 0; r < 8; ++r) idct1(p[r]);
#pragma unroll
    for (int c = 0; c < 8; ++c) {
      float t[8];
#pragma unroll
      for (int r = 0; r < 8; ++r) t[r] = p[r][c];
      idct1(t);
#pragma unroll
      for (int r = 0; r < 8; ++r) p[r][c] = t[r];
    }

    // store reconstructed YCbCr (+128) back to smem
#pragma unroll
    for (int r = 0; r < 8; ++r) {
      int R = br * 8 + r;
#pragma unroll
      for (int j = 0; j < 2; ++j) {
        int c = bc * 8 + j * 4;
        float4 v = make_float4(p[r][j * 4 + 0] + 128.f,
                               p[r][j * 4 + 1] + 128.f,
                               p[r][j * 4 + 2] + 128.f,
                               p[r][j * 4 + 3] + 128.f);
        *(float4*)&pl[swz(R, c)] = v;
      }
    }
  }

  __syncthreads();

  // ---------------- Phase 3: YCbCr -> RGB, clip, store ----------------
  float* __restrict__ qr = out + img;
  float* __restrict__ qg = out + img + plane;
  float* __restrict__ qb = out + img + 2 * plane;
#pragma unroll
  for (int it = 0; it < 4; ++it) {
    int i = tid + it * 256;
    int row = i >> 4;
    int c = (i & 15) << 2;
    int sw = swz(row, c);
    float4 y4  = *(const float4*)&sm[sw];
    float4 cb4 = *(const float4*)&sm[4096 + sw];
    float4 cr4 = *(const float4*)&sm[8192 + sw];

    float Yv[4] = { y4.x, y4.y, y4.z, y4.w };
    float Cb[4] = { cb4.x, cb4.y, cb4.z, cb4.w };
    float Cr[4] = { cr4.x, cr4.y, cr4.z, cr4.w };
    float R[4], G[4], Bv[4];
#pragma unroll
    for (int q = 0; q < 4; ++q) {
      float yy = Yv[q];
      float cb = Cb[q] - 128.f;
      float cr = Cr[q] - 128.f;
      float r = yy + 1.402f * cr;
      float g = yy - 0.344136f * cb - 0.714136f * cr;
      float b = yy + 1.772f * cb;
      const float inv255 = 1.0f / 255.0f;
      R[q]  = fminf(fmaxf(r, 0.f), 255.f) * inv255;
      G[q]  = fminf(fmaxf(g, 0.f), 255.f) * inv255;
      Bv[q] = fminf(fmaxf(b, 0.f), 255.f) * inv255;
    }
    size_t g = (size_t)(gy0 + row) * Ww + (gx0 + c);
    *(float4*)(qr + g) = make_float4(R[0], R[1], R[2], R[3]);
    *(float4*)(qg + g) = make_float4(G[0], G[1], G[2], G[3]);
    *(float4*)(qb + g) = make_float4(Bv[0], Bv[1], Bv[2], Bv[3]);
  }
}

} // namespace

extern "C" void kernel_launch(void* const* d_in, const int* in_sizes, int n_in,
                              void* d_out, int out_size) {
  (void)in_sizes; (void)n_in; (void)out_size;
  const float* in = (const float*)d_in[0];
  float* out = (float*)d_out;
  dim3 grid(Ww / 64, Hh / 64, 16);
  jpeg_kernel<<<grid, 256>>>(in, out);
}

// round 4
// speedup vs baseline: 1.0349x; 1.0349x over previous
#include <cuda_runtime.h>

// JPEG compress/decompress (DiffJPEG, factor=1.0) for [16,3,512,512] fp32 in [-1,1].
// One CTA = one 64x64 pixel tile, 256 threads, 4 CTAs/SM.
// Phases: 1) RGB->YCbCr to smem  2a) row DCT  2b) col DCT + quant + col IDCT
//         2c) row IDCT  3) YCbCr->RGB store.
// DC trick: instead of (p-128) before DCT and +128 after IDCT, subtract
// 128*64=8192 from the DC coefficient (exact) and fold +128 into phase 3.

namespace {

constexpr int Hh = 512;
constexpr int Ww = 512;

// DCT-II basis: Dm[u][x] = cos((2x+1) u pi / 16)
__device__ static constexpr float Dm[8][8] = {
  { 1.f,          1.f,          1.f,          1.f,          1.f,          1.f,          1.f,          1.f         },
  { 0.98078528f,  0.83146961f,  0.55557023f,  0.19509032f, -0.19509032f, -0.55557023f, -0.83146961f, -0.98078528f },
  { 0.92387953f,  0.38268343f, -0.38268343f, -0.92387953f, -0.92387953f, -0.38268343f,  0.38268343f,  0.92387953f },
  { 0.83146961f, -0.19509032f, -0.98078528f, -0.55557023f,  0.55557023f,  0.98078528f,  0.19509032f, -0.83146961f },
  { 0.70710678f, -0.70710678f, -0.70710678f,  0.70710678f,  0.70710678f, -0.70710678f, -0.70710678f,  0.70710678f },
  { 0.55557023f, -0.98078528f,  0.19509032f,  0.83146961f, -0.83146961f, -0.19509032f,  0.98078528f, -0.55557023f },
  { 0.38268343f, -0.92387953f,  0.92387953f, -0.38268343f, -0.38268343f,  0.92387953f, -0.92387953f,  0.38268343f },
  { 0.19509032f, -0.55557023f,  0.83146961f, -0.98078528f,  0.98078528f, -0.83146961f,  0.55557023f, -0.19509032f },
};

__device__ static const float QY[64] = {
  16, 11, 10, 16, 24, 40, 51, 61,
  12, 12, 14, 19, 26, 58, 60, 55,
  14, 13, 16, 24, 40, 57, 69, 56,
  14, 17, 22, 29, 51, 87, 80, 62,
  18, 22, 37, 56, 68, 109, 103, 77,
  24, 35, 55, 64, 81, 104, 113, 92,
  49, 64, 78, 87, 103, 121, 120, 101,
  72, 92, 95, 98, 112, 100, 103, 99
};
__device__ static const float QC[64] = {
  17, 18, 24, 47, 99, 99, 99, 99,
  18, 21, 26, 66, 99, 99, 99, 99,
  24, 26, 56, 99, 99, 99, 99, 99,
  47, 66, 99, 99, 99, 99, 99, 99,
  99, 99, 99, 99, 99, 99, 99, 99,
  99, 99, 99, 99, 99, 99, 99, 99,
  99, 99, 99, 99, 99, 99, 99, 99,
  99, 99, 99, 99, 99, 99, 99, 99
};

// smem column swizzle: XOR bit2 with bit5 so both linear-float4 and
// 8-strided-block accesses are bank-conflict-free.
__device__ __forceinline__ int swzc(int c) { return c ^ ((c & 32) >> 3); }

// 1D 8-point DCT (even/odd split): out[k] = sum_j in[j] * Dm[k][j]
__device__ __forceinline__ void dct1(float* v) {
  float e0 = v[0] + v[7], e1 = v[1] + v[6], e2 = v[2] + v[5], e3 = v[3] + v[4];
  float o0 = v[0] - v[7], o1 = v[1] - v[6], o2 = v[2] - v[5], o3 = v[3] - v[4];
  v[0] = (e0 + e3) + (e1 + e2);
  v[4] = Dm[4][0] * ((e0 + e3) - (e1 + e2));
  v[2] = Dm[2][0]*e0 + Dm[2][1]*e1 + Dm[2][2]*e2 + Dm[2][3]*e3;
  v[6] = Dm[6][0]*e0 + Dm[6][1]*e1 + Dm[6][2]*e2 + Dm[6][3]*e3;
  v[1] = Dm[1][0]*o0 + Dm[1][1]*o1 + Dm[1][2]*o2 + Dm[1][3]*o3;
  v[3] = Dm[3][0]*o0 + Dm[3][1]*o1 + Dm[3][2]*o2 + Dm[3][3]*o3;
  v[5] = Dm[5][0]*o0 + Dm[5][1]*o1 + Dm[5][2]*o2 + Dm[5][3]*o3;
  v[7] = Dm[7][0]*o0 + Dm[7][1]*o1 + Dm[7][2]*o2 + Dm[7][3]*o3;
}

// 1D 8-point IDCT: out[k] = sum_j in[j] * Dm[j][k]
__device__ __forceinline__ void idct1(float* v) {
  float i0 = v[0], i1 = v[1], i2 = v[2], i3 = v[3];
  float i4 = v[4], i5 = v[5], i6 = v[6], i7 = v[7];
#pragma unroll
  for (int k = 0; k < 4; ++k) {
    float ev = i0 + Dm[2][k]*i2 + Dm[4][k]*i4 + Dm[6][k]*i6;
    float od = Dm[1][k]*i1 + Dm[3][k]*i3 + Dm[5][k]*i5 + Dm[7][k]*i7;
    v[k]     = ev + od;
    v[7 - k] = ev - od;
  }
}

__global__ void __launch_bounds__(256, 4)
jpeg_kernel(const float* __restrict__ in, float* __restrict__ out) {
  extern __shared__ float sm[];         // 3*4096 plane + 128 SA + 128 SB
  float* sQA = sm + 12288;              // [tab*64 + u*8+v] = 0.25*au*av / Q
  float* sQB = sm + 12416;              // [tab*64 + u*8+v] = 0.25*au*av * Q

  const int tid = threadIdx.x;
  const int gx0 = blockIdx.x * 64;
  const int gy0 = blockIdx.y * 64;
  const size_t plane = (size_t)Hh * Ww;
  const size_t img = (size_t)blockIdx.z * 3 * plane;
  const float* __restrict__ pr = in + img;
  const float* __restrict__ pg = in + img + plane;
  const float* __restrict__ pb = in + img + 2 * plane;

  // ---- quant table fill (before first barrier) ----
  if (tid < 128) {
    int tab = tid >> 6, uv = tid & 63, u = uv >> 3, v = uv & 7;
    float a = 0.25f * (u ? 1.f : 0.70710678118654752f)
                    * (v ? 1.f : 0.70710678118654752f);
    float Q = tab ? QC[uv] : QY[uv];
    sQA[tid] = a / Q;
    sQB[tid] = a * Q;
  }

  // ---------------- Phase 1: RGB -> YCbCr into smem ----------------
#pragma unroll
  for (int it = 0; it < 4; ++it) {
    int i = tid + it * 256;             // float4 slot in tile
    int row = i >> 4;
    int c = (i & 15) << 2;
    size_t g = (size_t)(gy0 + row) * Ww + (gx0 + c);
    float4 r4 = *(const float4*)(pr + g);
    float4 g4 = *(const float4*)(pg + g);
    float4 b4 = *(const float4*)(pb + g);

    float R[4] = { r4.x, r4.y, r4.z, r4.w };
    float G[4] = { g4.x, g4.y, g4.z, g4.w };
    float Bv[4] = { b4.x, b4.y, b4.z, b4.w };
    float Yv[4], Cb[4], Cr[4];
#pragma unroll
    for (int q = 0; q < 4; ++q) {
      // fold (x+1)/2*255 into the 3x3: coeff*127.5, Y const = 127.5, C const = 128
      Yv[q] = fmaf(38.1225f, R[q], fmaf(74.8425f, G[q], fmaf(14.535f, Bv[q], 127.5f)));
      Cb[q] = fmaf(-21.51384f, R[q], fmaf(-42.23616f, G[q], fmaf(63.75f, Bv[q], 128.f)));
      Cr[q] = fmaf(63.75f, R[q], fmaf(-53.38272f, G[q], fmaf(-10.36728f, Bv[q], 128.f)));
    }
    int sw = row * 64 + swzc(c);
    *(float4*)&sm[sw]        = make_float4(Yv[0], Yv[1], Yv[2], Yv[3]);
    *(float4*)&sm[4096 + sw] = make_float4(Cb[0], Cb[1], Cb[2], Cb[3]);
    *(float4*)&sm[8192 + sw] = make_float4(Cr[0], Cr[1], Cr[2], Cr[3]);
  }
  __syncthreads();

  // ---------------- Phase 2a: row DCT (1536 row-vectors) ----------------
#pragma unroll
  for (int it = 0; it < 6; ++it) {
    int j = tid + it * 256;
    int k = j >> 9, rem = j & 511;
    int row = rem >> 3, bc = (rem & 7) << 3;
    int base = k * 4096 + row * 64;
    float vec[8];
    float4 a = *(const float4*)&sm[base + swzc(bc)];
    float4 b = *(const float4*)&sm[base + swzc(bc + 4)];
    vec[0]=a.x; vec[1]=a.y; vec[2]=a.z; vec[3]=a.w;
    vec[4]=b.x; vec[5]=b.y; vec[6]=b.z; vec[7]=b.w;
    dct1(vec);
    *(float4*)&sm[base + swzc(bc)]     = make_float4(vec[0],vec[1],vec[2],vec[3]);
    *(float4*)&sm[base + swzc(bc + 4)] = make_float4(vec[4],vec[5],vec[6],vec[7]);
  }
  __syncthreads();

  // ------- Phase 2b: col DCT + quantize(diff-round) + col IDCT -------
#pragma unroll
  for (int it = 0; it < 6; ++it) {
    int j = tid + it * 256;
    int k = j >> 9, rem = j & 511;
    int col = rem & 63, br = rem >> 6;
    int v = col & 7;
    int base = k * 4096 + br * 512 + swzc(col);
    float vec[8];
#pragma unroll
    for (int r = 0; r < 8; ++r) vec[r] = sm[base + r * 64];
    dct1(vec);
    if (v == 0) vec[0] -= 8192.f;       // DC: equivalent of (p-128) pre-DCT
    const float* qa = &sQA[(k ? 64 : 0) + v];
    const float* qb = &sQB[(k ? 64 : 0) + v];
#pragma unroll
    for (int u = 0; u < 8; ++u) {
      float s = vec[u] * qa[u * 8];
      float r = rintf(s);               // half-to-even == jnp.round
      float d = s - r;
      vec[u] = fmaf(d * d, d, r) * qb[u * 8];
    }
    idct1(vec);
#pragma unroll
    for (int r = 0; r < 8; ++r) sm[base + r * 64] = vec[r];
  }
  __syncthreads();

  // ---------------- Phase 2c: row IDCT ----------------
#pragma unroll
  for (int it = 0; it < 6; ++it) {
    int j = tid + it * 256;
    int k = j >> 9, rem = j & 511;
    int row = rem >> 3, bc = (rem & 7) << 3;
    int base = k * 4096 + row * 64;
    float vec[8];
    float4 a = *(const float4*)&sm[base + swzc(bc)];
    float4 b = *(const float4*)&sm[base + swzc(bc + 4)];
    vec[0]=a.x; vec[1]=a.y; vec[2]=a.z; vec[3]=a.w;
    vec[4]=b.x; vec[5]=b.y; vec[6]=b.z; vec[7]=b.w;
    idct1(vec);
    *(float4*)&sm[base + swzc(bc)]     = make_float4(vec[0],vec[1],vec[2],vec[3]);
    *(float4*)&sm[base + swzc(bc + 4)] = make_float4(vec[4],vec[5],vec[6],vec[7]);
  }
  __syncthreads();

  // ------------- Phase 3: YCbCr -> RGB, clip, store -------------
  // smem now holds recon-128 in all channels (DC trick); so
  // y = Y'+128, cb = Cb' (already centered), cr = Cr'.
  float* __restrict__ qr = out + img;
  float* __restrict__ qg = out + img + plane;
  float* __restrict__ qb = out + img + 2 * plane;
#pragma unroll
  for (int it = 0; it < 4; ++it) {
    int i = tid + it * 256;
    int row = i >> 4;
    int c = (i & 15) << 2;
    int sw = row * 64 + swzc(c);
    float4 y4  = *(const float4*)&sm[sw];
    float4 cb4 = *(const float4*)&sm[4096 + sw];
    float4 cr4 = *(const float4*)&sm[8192 + sw];

    float Yv[4] = { y4.x, y4.y, y4.z, y4.w };
    float Cb[4] = { cb4.x, cb4.y, cb4.z, cb4.w };
    float Cr[4] = { cr4.x, cr4.y, cr4.z, cr4.w };
    float R[4], G[4], Bv[4];
#pragma unroll
    for (int q = 0; q < 4; ++q) {
      float y128 = Yv[q] + 128.f;
      float cb = Cb[q];
      float cr = Cr[q];
      float r = fmaf(1.402f, cr, y128);
      float g = fmaf(-0.714136f, cr, fmaf(-0.344136f, cb, y128));
      float b = fmaf(1.772f, cb, y128);
      const float inv255 = 1.0f / 255.0f;
      R[q]  = fminf(fmaxf(r, 0.f), 255.f) * inv255;
      G[q]  = fminf(fmaxf(g, 0.f), 255.f) * inv255;
      Bv[q] = fminf(fmaxf(b, 0.f), 255.f) * inv255;
    }
    size_t g = (size_t)(gy0 + row) * Ww + (gx0 + c);
    *(float4*)(qr + g) = make_float4(R[0], R[1], R[2], R[3]);
    *(float4*)(qg + g) = make_float4(G[0], G[1], G[2], G[3]);
    *(float4*)(qb + g) = make_float4(Bv[0], Bv[1], Bv[2], Bv[3]);
  }
}

} // namespace

extern "C" void kernel_launch(void* const* d_in, const int* in_sizes, int n_in,
                              void* d_out, int out_size) {
  (void)in_sizes; (void)n_in; (void)out_size;
  const float* in = (const float*)d_in[0];
  float* out = (float*)d_out;
  constexpr int SMEM = (3 * 4096 + 256) * 4;   // 50176 bytes
  static bool attr_set = false;
  if (!attr_set) {
    cudaFuncSetAttribute(jpeg_kernel, cudaFuncAttributeMaxDynamicSharedMemorySize, SMEM);
    attr_set = true;
  }
  dim3 grid(Ww / 64, Hh / 64, 16);
  jpeg_kernel<<<grid, 256, SMEM>>>(in, out);
}